// round 11
// baseline (speedup 1.0000x reference)
#include <cuda_runtime.h>

// Shapes (fixed): n=1024 tokens, 2L=512, H=512, H2=256.
#define NTOK 1024
#define KIN  512
#define HH   512
#define H2D  256
#define SCALE_2LOG2E 2.885390081777927f   // 2*log2(e)

// Scratch (device globals; no allocations allowed)
__device__ float g_ah[NTOK * HH];
__device__ float g_am[NTOK * HH];
__device__ float g_Ep[NTOK * H2D];  // ex2(c*A)             (head side)
__device__ float g_Eq[NTOK * H2D];  // ex2(c*(B + h2bias))  (mod side)
__device__ float g_C;               // sum(w) + outBias

// tanh(x) = 1 - 2/(exp(2x)+1); exact tails, ~1e-6 rel error.
__device__ __forceinline__ float fast_tanh(float x) {
    float e;
    asm("ex2.approx.f32 %0, %1;" : "=f"(e) : "f"(x * SCALE_2LOG2E));
    float r;
    asm("rcp.approx.f32 %0, %1;" : "=f"(r) : "f"(e + 1.0f));
    return 1.0f - 2.0f * r;
}

__device__ __forceinline__ float fast_ex2(float x) {
    float e;
    asm("ex2.approx.f32 %0, %1;" : "=f"(e) : "f"(x));
    return e;
}

// ---------------------------------------------------------------------------
// Kernel 1: [ah | am] = tanh( x @ [W_foh | W_fom] + catBias )
// 64x64 tile, BK=16, 256 threads, 4x4 micro, double-buffered smem.
// Grid (16,16) = 256 blocks.
// ---------------------------------------------------------------------------
__global__ __launch_bounds__(256)
void gemm1_tanh(const float* __restrict__ l0, const float* __restrict__ l1,
                const float* __restrict__ Wfoh, const float* __restrict__ Wfom,
                const float* __restrict__ catBias) {
    __shared__ __align__(16) float As[2][16][68];   // As[buf][k][m]
    __shared__ __align__(16) float Bs[2][16][68];   // Bs[buf][k][n]

    const int tid = threadIdx.x;
    const int n0 = blockIdx.x * 64;        // combined N (0..1023)
    const int m0 = blockIdx.y * 64;

    const bool head = (n0 < 512);
    const float* __restrict__ W = head ? Wfoh : Wfom;
    const int   wcol = head ? n0 : (n0 - 512);
    float* __restrict__ out = head ? g_ah : g_am;

    const int tx = tid & 15;
    const int ty = tid >> 4;
    const int lm  = tid >> 2;              // 0..63 (A rows)
    const int lk4 = (tid & 3) * 4;         // 0,4,8,12
    const int lk  = tid >> 4;              // 0..15 (B k)
    const int ln  = (tid & 15) * 4;        // 0..60 (B n)

    // prologue load k0 = 0
    float4 av = *(const float4*)(l0 + (size_t)(m0 + lm) * 256 + lk4);
    float4 bv = *(const float4*)(W + (size_t)lk * HH + wcol + ln);
    As[0][lk4 + 0][lm] = av.x;
    As[0][lk4 + 1][lm] = av.y;
    As[0][lk4 + 2][lm] = av.z;
    As[0][lk4 + 3][lm] = av.w;
    *(float4*)&Bs[0][lk][ln] = bv;
    __syncthreads();

    float acc[4][4] = {};
    int cur = 0;

    for (int k0 = 0; k0 < KIN; k0 += 16) {
        float4 av2, bv2;
        const int kn = k0 + 16;
        if (kn < KIN) {
            const float* __restrict__ xsrc =
                (kn < 256) ? (l0 + (size_t)(m0 + lm) * 256 + (kn + lk4))
                           : (l1 + (size_t)(m0 + lm) * 256 + (kn - 256 + lk4));
            av2 = *(const float4*)xsrc;
            bv2 = *(const float4*)(W + (size_t)(kn + lk) * HH + wcol + ln);
        }

#pragma unroll
        for (int kk = 0; kk < 16; kk++) {
            float4 a4 = *(const float4*)&As[cur][kk][ty * 4];
            float4 b4 = *(const float4*)&Bs[cur][kk][tx * 4];
            float aa[4] = {a4.x, a4.y, a4.z, a4.w};
            float bb[4] = {b4.x, b4.y, b4.z, b4.w};
#pragma unroll
            for (int i = 0; i < 4; i++)
#pragma unroll
                for (int j = 0; j < 4; j++)
                    acc[i][j] = fmaf(aa[i], bb[j], acc[i][j]);
        }

        if (kn < KIN) {
            const int nxt = cur ^ 1;
            As[nxt][lk4 + 0][lm] = av2.x;
            As[nxt][lk4 + 1][lm] = av2.y;
            As[nxt][lk4 + 2][lm] = av2.z;
            As[nxt][lk4 + 3][lm] = av2.w;
            *(float4*)&Bs[nxt][lk][ln] = bv2;
            __syncthreads();
            cur = nxt;
        }
    }

    const float4 bias4 = *(const float4*)&catBias[n0 + tx * 4];
#pragma unroll
    for (int i = 0; i < 4; i++) {
        float4 v;
        v.x = fast_tanh(acc[i][0] + bias4.x);
        v.y = fast_tanh(acc[i][1] + bias4.y);
        v.z = fast_tanh(acc[i][2] + bias4.z);
        v.w = fast_tanh(acc[i][3] + bias4.w);
        *(float4*)&out[(size_t)(m0 + ty * 4 + i) * HH + wcol + tx * 4] = v;
    }
}

// ---------------------------------------------------------------------------
// Kernel 2: Ep = ex2( c * (ah @ hid2Layer[0:512]) )
//           Eq = ex2( c * (am @ hid2Layer[512:1024] + hid2Bias) )
// 64x64 tile, BK=16, 256 threads, 4x4 micro, double-buffered.
// Grid (8,16) = 128 blocks.
// ---------------------------------------------------------------------------
__global__ __launch_bounds__(256)
void gemm2_exp(const float* __restrict__ h2L, const float* __restrict__ h2B) {
    __shared__ __align__(16) float As[2][16][68];
    __shared__ __align__(16) float Bs[2][16][68];

    const int tid = threadIdx.x;
    const int n0 = blockIdx.x * 64;        // combined N (0..511)
    const int m0 = blockIdx.y * 64;

    const bool isP = (n0 < 256);
    const float* __restrict__ Asrc = isP ? g_ah : g_am;
    const int   wrow = isP ? 0 : 512;
    const int   col0 = isP ? n0 : (n0 - 256);
    float* __restrict__ out = isP ? g_Ep : g_Eq;

    const int tx = tid & 15;
    const int ty = tid >> 4;
    const int lm  = tid >> 2;
    const int lk4 = (tid & 3) * 4;
    const int lk  = tid >> 4;
    const int ln  = (tid & 15) * 4;

    float4 av = *(const float4*)(Asrc + (size_t)(m0 + lm) * HH + lk4);
    float4 bv = *(const float4*)(h2L + (size_t)(wrow + lk) * H2D + col0 + ln);
    As[0][lk4 + 0][lm] = av.x;
    As[0][lk4 + 1][lm] = av.y;
    As[0][lk4 + 2][lm] = av.z;
    As[0][lk4 + 3][lm] = av.w;
    *(float4*)&Bs[0][lk][ln] = bv;
    __syncthreads();

    float acc[4][4] = {};
    int cur = 0;

    for (int k0 = 0; k0 < HH; k0 += 16) {
        float4 av2, bv2;
        const int kn = k0 + 16;
        if (kn < HH) {
            av2 = *(const float4*)(Asrc + (size_t)(m0 + lm) * HH + kn + lk4);
            bv2 = *(const float4*)(h2L + (size_t)(wrow + kn + lk) * H2D + col0 + ln);
        }

#pragma unroll
        for (int kk = 0; kk < 16; kk++) {
            float4 a4 = *(const float4*)&As[cur][kk][ty * 4];
            float4 b4 = *(const float4*)&Bs[cur][kk][tx * 4];
            float aa[4] = {a4.x, a4.y, a4.z, a4.w};
            float bb[4] = {b4.x, b4.y, b4.z, b4.w};
#pragma unroll
            for (int i = 0; i < 4; i++)
#pragma unroll
                for (int j = 0; j < 4; j++)
                    acc[i][j] = fmaf(aa[i], bb[j], acc[i][j]);
        }

        if (kn < HH) {
            const int nxt = cur ^ 1;
            As[nxt][lk4 + 0][lm] = av2.x;
            As[nxt][lk4 + 1][lm] = av2.y;
            As[nxt][lk4 + 2][lm] = av2.z;
            As[nxt][lk4 + 3][lm] = av2.w;
            *(float4*)&Bs[nxt][lk][ln] = bv2;
            __syncthreads();
            cur = nxt;
        }
    }

#pragma unroll
    for (int j = 0; j < 4; j++) {
        const float bias = isP ? 0.0f : h2B[col0 + tx * 4 + j];
#pragma unroll
        for (int i = 0; i < 4; i++) {
            float v = fast_ex2((acc[i][j] + bias) * SCALE_2LOG2E);
            out[(size_t)(m0 + ty * 4 + i) * H2D + col0 + tx * 4 + j] = v;
        }
    }
}

// ---------------------------------------------------------------------------
// Kernel 3: g_C = sum(outLayer) + outBias
// ---------------------------------------------------------------------------
__global__ void sumw_kernel(const float* __restrict__ outL,
                            const float* __restrict__ outB) {
    __shared__ float s[256];
    s[threadIdx.x] = outL[threadIdx.x];
    __syncthreads();
    for (int o = 128; o > 0; o >>= 1) {
        if (threadIdx.x < o) s[threadIdx.x] += s[threadIdx.x + o];
        __syncthreads();
    }
    if (threadIdx.x == 0) g_C = s[0] + outB[0];
}

// ---------------------------------------------------------------------------
// Kernel 4: pairwise scores (1 MUFU + 2 FMA per element):
//   scores[i,j] = C + sum_h (-2*w_h) * rcp( Ep[i,h]*Eq[j,h] + 1 )
// 64x64 output tile per block, 256 threads, 4x4 micro-tile per thread
// (rows ty+16r, cols tx+16c). h processed in 4 chunks of 64.
// Grid 256 blocks = one wave. Per h4 step: 64 MUFU vs 9 LDS.128 (Ep/w
// broadcast; Eq conflict-free via 68-float row padding).
// ---------------------------------------------------------------------------
__device__ __forceinline__ float pterm(float ep, float eq, float w, float acc) {
    float t = fmaf(ep, eq, 1.0f);
    float r;
    asm("rcp.approx.f32 %0, %1;" : "=f"(r) : "f"(t));
    return fmaf(w, r, acc);
}

__global__ __launch_bounds__(256, 2)
void pairwise_kernel(const float* __restrict__ outL, float* __restrict__ out) {
    __shared__ __align__(16) float Eps[64][68];
    __shared__ __align__(16) float Eqs[64][68];
    __shared__ __align__(16) float ws[256];

    const int tid = threadIdx.x;
    ws[tid] = -2.0f * outL[tid];

    const int j0 = (blockIdx.x & 15) * 64;
    const int i0 = (blockIdx.x >> 4) * 64;

    const int tx = tid & 15;
    const int ty = tid >> 4;

    float acc[4][4] = {};

    for (int ch = 0; ch < 4; ch++) {
        __syncthreads();   // ws visible (ch=0) / prior chunk reads done
#pragma unroll
        for (int p = 0; p < 4; p++) {
            int lin = tid + p * 256;
            int row = lin >> 4;            // 0..63
            int c   = (lin & 15) * 4;      // 0..60
            *(float4*)&Eps[row][c] =
                *(const float4*)&g_Ep[(size_t)(i0 + row) * H2D + ch * 64 + c];
            *(float4*)&Eqs[row][c] =
                *(const float4*)&g_Eq[(size_t)(j0 + row) * H2D + ch * 64 + c];
        }
        __syncthreads();

        const float* __restrict__ pw = &ws[ch * 64];
#pragma unroll 2
        for (int h4 = 0; h4 < 16; h4++) {
            float4 a[4], b[4];
#pragma unroll
            for (int r = 0; r < 4; r++)
                a[r] = *(const float4*)&Eps[ty + 16 * r][h4 * 4];
#pragma unroll
            for (int c = 0; c < 4; c++)
                b[c] = *(const float4*)&Eqs[tx + 16 * c][h4 * 4];
            float4 w4 = *(const float4*)(pw + h4 * 4);

#pragma unroll
            for (int r = 0; r < 4; r++) {
#pragma unroll
                for (int c = 0; c < 4; c++) {
                    acc[r][c] = pterm(a[r].x, b[c].x, w4.x, acc[r][c]);
                    acc[r][c] = pterm(a[r].y, b[c].y, w4.y, acc[r][c]);
                    acc[r][c] = pterm(a[r].z, b[c].z, w4.z, acc[r][c]);
                    acc[r][c] = pterm(a[r].w, b[c].w, w4.w, acc[r][c]);
                }
            }
        }
    }

    const float C = g_C;
#pragma unroll
    for (int r = 0; r < 4; r++)
#pragma unroll
        for (int c = 0; c < 4; c++)
            out[(size_t)(i0 + ty + 16 * r) * NTOK + (j0 + tx + 16 * c)]
                = C + acc[r][c];
}

// ---------------------------------------------------------------------------
extern "C" void kernel_launch(void* const* d_in, const int* in_sizes, int n_in,
                              void* d_out, int out_size) {
    const float* l0   = (const float*)d_in[0];   // lstms0 [1024,256]
    const float* l1   = (const float*)d_in[1];   // lstms1 [1024,256]
    const float* Wfoh = (const float*)d_in[2];   // [512,512]
    const float* Wfom = (const float*)d_in[3];   // [512,512]
    const float* catB = (const float*)d_in[4];   // [1,1024]
    const float* h2L  = (const float*)d_in[5];   // [1024,256]
    const float* h2B  = (const float*)d_in[6];   // [1,256]
    const float* outL = (const float*)d_in[7];   // [256,1]
    const float* outB = (const float*)d_in[8];   // [1,1]
    float* out = (float*)d_out;                  // [1024,1024]

    gemm1_tanh<<<dim3(16, 16), 256>>>(l0, l1, Wfoh, Wfom, catB);
    gemm2_exp<<<dim3(8, 16), 256>>>(h2L, h2B);
    sumw_kernel<<<1, 256>>>(outL, outB);
    pairwise_kernel<<<256, 256>>>(outL, out);
}

// round 12
// speedup vs baseline: 1.0460x; 1.0460x over previous
#include <cuda_runtime.h>
#include <cstdint>

// Shapes (fixed): n=1024 tokens, 2L=512, H=512, H2=256.
#define NTOK 1024
#define KIN  512
#define HH   512
#define H2D  256
#define SCALE_2LOG2E 2.885390081777927f   // 2*log2(e)
#define ONE2 0x3F8000003F800000ULL        // (1.0f, 1.0f) packed

// Scratch (device globals; no allocations allowed)
__device__ float g_ah[NTOK * HH];
__device__ float g_am[NTOK * HH];
__device__ float g_Ep[NTOK * H2D];  // ex2(c*A)             (head side)
__device__ float g_Eq[NTOK * H2D];  // ex2(c*(B + h2bias))  (mod side)
__device__ float g_C;               // sum(w) + outBias

// ---------------- packed f32x2 helpers (sm_103a FFMA2 path) ----------------
__device__ __forceinline__ uint64_t fma2(uint64_t a, uint64_t b, uint64_t c) {
    uint64_t d;
    asm("fma.rn.f32x2 %0, %1, %2, %3;" : "=l"(d) : "l"(a), "l"(b), "l"(c));
    return d;
}
__device__ __forceinline__ uint64_t pack2(float lo, float hi) {
    uint64_t d;
    asm("mov.b64 %0, {%1, %2};" : "=l"(d) : "f"(lo), "f"(hi));
    return d;
}
__device__ __forceinline__ void unpack2(uint64_t p, float& lo, float& hi) {
    asm("mov.b64 {%0, %1}, %2;" : "=f"(lo), "=f"(hi) : "l"(p));
}
__device__ __forceinline__ uint64_t splat2(float v) {
    uint64_t d;
    asm("mov.b64 %0, {%1, %1};" : "=l"(d) : "f"(v));
    return d;
}
__device__ __forceinline__ float rcpf(float x) {
    float r;
    asm("rcp.approx.f32 %0, %1;" : "=f"(r) : "f"(x));
    return r;
}
__device__ __forceinline__ float fast_tanh(float x) {   // 1 - 2/(exp(2x)+1)
    float e;
    asm("ex2.approx.f32 %0, %1;" : "=f"(e) : "f"(x * SCALE_2LOG2E));
    return 1.0f - 2.0f * rcpf(e + 1.0f);
}
__device__ __forceinline__ float fast_ex2(float x) {
    float e;
    asm("ex2.approx.f32 %0, %1;" : "=f"(e) : "f"(x));
    return e;
}

// ---------------------------------------------------------------------------
// Kernel 1: [ah | am] = tanh( x @ [W_foh | W_fom] + catBias )
// 64x64 tile, BK=16, 256 threads, 4x4 micro (acc packed f32x2 along j),
// double-buffered smem. Grid (16,16) = 256 blocks.
// ---------------------------------------------------------------------------
__global__ __launch_bounds__(256)
void gemm1_tanh(const float* __restrict__ l0, const float* __restrict__ l1,
                const float* __restrict__ Wfoh, const float* __restrict__ Wfom,
                const float* __restrict__ catBias) {
    __shared__ __align__(16) float As[2][16][68];   // As[buf][k][m]
    __shared__ __align__(16) float Bs[2][16][68];   // Bs[buf][k][n]

    const int tid = threadIdx.x;
    const int n0 = blockIdx.x * 64;        // combined N (0..1023)
    const int m0 = blockIdx.y * 64;

    const bool head = (n0 < 512);
    const float* __restrict__ W = head ? Wfoh : Wfom;
    const int   wcol = head ? n0 : (n0 - 512);
    float* __restrict__ out = head ? g_ah : g_am;

    const int tx = tid & 15;
    const int ty = tid >> 4;
    const int lm  = tid >> 2;              // 0..63 (A rows)
    const int lk4 = (tid & 3) * 4;         // 0,4,8,12
    const int lk  = tid >> 4;              // 0..15 (B k)
    const int ln  = (tid & 15) * 4;        // 0..60 (B n)

    // prologue load k0 = 0
    float4 av = *(const float4*)(l0 + (size_t)(m0 + lm) * 256 + lk4);
    float4 bv = *(const float4*)(W + (size_t)lk * HH + wcol + ln);
    As[0][lk4 + 0][lm] = av.x;
    As[0][lk4 + 1][lm] = av.y;
    As[0][lk4 + 2][lm] = av.z;
    As[0][lk4 + 3][lm] = av.w;
    *(float4*)&Bs[0][lk][ln] = bv;
    __syncthreads();

    uint64_t accP[4][2] = {};              // [i][j-pair], f32x2
    int cur = 0;

    for (int k0 = 0; k0 < KIN; k0 += 16) {
        float4 av2, bv2;
        const int kn = k0 + 16;
        if (kn < KIN) {
            const float* __restrict__ xsrc =
                (kn < 256) ? (l0 + (size_t)(m0 + lm) * 256 + (kn + lk4))
                           : (l1 + (size_t)(m0 + lm) * 256 + (kn - 256 + lk4));
            av2 = *(const float4*)xsrc;
            bv2 = *(const float4*)(W + (size_t)(kn + lk) * HH + wcol + ln);
        }

#pragma unroll
        for (int kk = 0; kk < 16; kk++) {
            float4 a4 = *(const float4*)&As[cur][kk][ty * 4];
            ulonglong2 b2 = *(const ulonglong2*)&Bs[cur][kk][tx * 4];
            float aa[4] = {a4.x, a4.y, a4.z, a4.w};
#pragma unroll
            for (int i = 0; i < 4; i++) {
                uint64_t as = splat2(aa[i]);
                accP[i][0] = fma2(as, b2.x, accP[i][0]);
                accP[i][1] = fma2(as, b2.y, accP[i][1]);
            }
        }

        if (kn < KIN) {
            const int nxt = cur ^ 1;
            As[nxt][lk4 + 0][lm] = av2.x;
            As[nxt][lk4 + 1][lm] = av2.y;
            As[nxt][lk4 + 2][lm] = av2.z;
            As[nxt][lk4 + 3][lm] = av2.w;
            *(float4*)&Bs[nxt][lk][ln] = bv2;
            __syncthreads();
            cur = nxt;
        }
    }

    const float4 bias4 = *(const float4*)&catBias[n0 + tx * 4];
#pragma unroll
    for (int i = 0; i < 4; i++) {
        float s0, s1, s2, s3;
        unpack2(accP[i][0], s0, s1);
        unpack2(accP[i][1], s2, s3);
        float4 v;
        v.x = fast_tanh(s0 + bias4.x);
        v.y = fast_tanh(s1 + bias4.y);
        v.z = fast_tanh(s2 + bias4.z);
        v.w = fast_tanh(s3 + bias4.w);
        *(float4*)&out[(size_t)(m0 + ty * 4 + i) * HH + wcol + tx * 4] = v;
    }
}

// ---------------------------------------------------------------------------
// Kernel 2: Ep = ex2( c * (ah @ hid2Layer[0:512]) )
//           Eq = ex2( c * (am @ hid2Layer[512:1024] + hid2Bias) )
// Same structure as kernel 1. Grid (8,16) = 128 blocks.
// ---------------------------------------------------------------------------
__global__ __launch_bounds__(256)
void gemm2_exp(const float* __restrict__ h2L, const float* __restrict__ h2B) {
    __shared__ __align__(16) float As[2][16][68];
    __shared__ __align__(16) float Bs[2][16][68];

    const int tid = threadIdx.x;
    const int n0 = blockIdx.x * 64;        // combined N (0..511)
    const int m0 = blockIdx.y * 64;

    const bool isP = (n0 < 256);
    const float* __restrict__ Asrc = isP ? g_ah : g_am;
    const int   wrow = isP ? 0 : 512;
    const int   col0 = isP ? n0 : (n0 - 256);
    float* __restrict__ out = isP ? g_Ep : g_Eq;

    const int tx = tid & 15;
    const int ty = tid >> 4;
    const int lm  = tid >> 2;
    const int lk4 = (tid & 3) * 4;
    const int lk  = tid >> 4;
    const int ln  = (tid & 15) * 4;

    float4 av = *(const float4*)(Asrc + (size_t)(m0 + lm) * HH + lk4);
    float4 bv = *(const float4*)(h2L + (size_t)(wrow + lk) * H2D + col0 + ln);
    As[0][lk4 + 0][lm] = av.x;
    As[0][lk4 + 1][lm] = av.y;
    As[0][lk4 + 2][lm] = av.z;
    As[0][lk4 + 3][lm] = av.w;
    *(float4*)&Bs[0][lk][ln] = bv;
    __syncthreads();

    uint64_t accP[4][2] = {};
    int cur = 0;

    for (int k0 = 0; k0 < HH; k0 += 16) {
        float4 av2, bv2;
        const int kn = k0 + 16;
        if (kn < HH) {
            av2 = *(const float4*)(Asrc + (size_t)(m0 + lm) * HH + kn + lk4);
            bv2 = *(const float4*)(h2L + (size_t)(wrow + kn + lk) * H2D + col0 + ln);
        }

#pragma unroll
        for (int kk = 0; kk < 16; kk++) {
            float4 a4 = *(const float4*)&As[cur][kk][ty * 4];
            ulonglong2 b2 = *(const ulonglong2*)&Bs[cur][kk][tx * 4];
            float aa[4] = {a4.x, a4.y, a4.z, a4.w};
#pragma unroll
            for (int i = 0; i < 4; i++) {
                uint64_t as = splat2(aa[i]);
                accP[i][0] = fma2(as, b2.x, accP[i][0]);
                accP[i][1] = fma2(as, b2.y, accP[i][1]);
            }
        }

        if (kn < HH) {
            const int nxt = cur ^ 1;
            As[nxt][lk4 + 0][lm] = av2.x;
            As[nxt][lk4 + 1][lm] = av2.y;
            As[nxt][lk4 + 2][lm] = av2.z;
            As[nxt][lk4 + 3][lm] = av2.w;
            *(float4*)&Bs[nxt][lk][ln] = bv2;
            __syncthreads();
            cur = nxt;
        }
    }

#pragma unroll
    for (int i = 0; i < 4; i++) {
        float s0, s1, s2, s3;
        unpack2(accP[i][0], s0, s1);
        unpack2(accP[i][1], s2, s3);
        float b0 = isP ? 0.0f : h2B[col0 + tx * 4 + 0];
        float b1 = isP ? 0.0f : h2B[col0 + tx * 4 + 1];
        float b2 = isP ? 0.0f : h2B[col0 + tx * 4 + 2];
        float b3 = isP ? 0.0f : h2B[col0 + tx * 4 + 3];
        float4 v;
        v.x = fast_ex2((s0 + b0) * SCALE_2LOG2E);
        v.y = fast_ex2((s1 + b1) * SCALE_2LOG2E);
        v.z = fast_ex2((s2 + b2) * SCALE_2LOG2E);
        v.w = fast_ex2((s3 + b3) * SCALE_2LOG2E);
        *(float4*)&out[(size_t)(m0 + ty * 4 + i) * H2D + col0 + tx * 4] = v;
    }
}

// ---------------------------------------------------------------------------
// Kernel 3: g_C = sum(outLayer) + outBias
// ---------------------------------------------------------------------------
__global__ void sumw_kernel(const float* __restrict__ outL,
                            const float* __restrict__ outB) {
    __shared__ float s[256];
    s[threadIdx.x] = outL[threadIdx.x];
    __syncthreads();
    for (int o = 128; o > 0; o >>= 1) {
        if (threadIdx.x < o) s[threadIdx.x] += s[threadIdx.x + o];
        __syncthreads();
    }
    if (threadIdx.x == 0) g_C = s[0] + outB[0];
}

// ---------------------------------------------------------------------------
// Kernel 4: pairwise scores:
//   scores[i,j] = C + sum_h (-2*w_h) * rcp( Ep[i,h]*Eq[j,h] + 1 )
// 64x64 tile / block, 256 threads, 4x4 micro (rows ty+16r, cols tx+16c).
// Accumulators are f32x2 pairs over even/odd h: per 2 h-elements the math is
// 1 FFMA2 (t-pair) + 2 RCP + 1 pack + 1 FFMA2 (acc) -> issue stream ~2.5
// slots/element vs 8 MUFU pipe-cycles/element, so MUFU binds.
// ---------------------------------------------------------------------------
__device__ __forceinline__ void pstep(uint64_t ep2, uint64_t eq2, uint64_t w2,
                                      uint64_t& acc2) {
    uint64_t t2 = fma2(ep2, eq2, (uint64_t)ONE2);
    float t0, t1;
    unpack2(t2, t0, t1);
    uint64_t r2 = pack2(rcpf(t0), rcpf(t1));
    acc2 = fma2(w2, r2, acc2);
}

__global__ __launch_bounds__(256, 2)
void pairwise_kernel(const float* __restrict__ outL, float* __restrict__ out) {
    __shared__ __align__(16) float Eps[64][68];
    __shared__ __align__(16) float Eqs[64][68];
    __shared__ __align__(16) float ws[256];

    const int tid = threadIdx.x;
    ws[tid] = -2.0f * outL[tid];

    const int j0 = (blockIdx.x & 15) * 64;
    const int i0 = (blockIdx.x >> 4) * 64;

    const int tx = tid & 15;
    const int ty = tid >> 4;

    uint64_t accP[4][4] = {};   // f32x2: lo = even h, hi = odd h

    for (int ch = 0; ch < 4; ch++) {
        __syncthreads();   // ws visible (ch=0) / prior chunk reads done
#pragma unroll
        for (int p = 0; p < 4; p++) {
            int lin = tid + p * 256;
            int row = lin >> 4;            // 0..63
            int c   = (lin & 15) * 4;      // 0..60
            *(float4*)&Eps[row][c] =
                *(const float4*)&g_Ep[(size_t)(i0 + row) * H2D + ch * 64 + c];
            *(float4*)&Eqs[row][c] =
                *(const float4*)&g_Eq[(size_t)(j0 + row) * H2D + ch * 64 + c];
        }
        __syncthreads();

        const float* __restrict__ pw = &ws[ch * 64];
#pragma unroll 2
        for (int h4 = 0; h4 < 16; h4++) {
            ulonglong2 aP[4], bP[4];
#pragma unroll
            for (int r = 0; r < 4; r++)
                aP[r] = *(const ulonglong2*)&Eps[ty + 16 * r][h4 * 4];
#pragma unroll
            for (int c = 0; c < 4; c++)
                bP[c] = *(const ulonglong2*)&Eqs[tx + 16 * c][h4 * 4];
            ulonglong2 wP = *(const ulonglong2*)(pw + h4 * 4);

#pragma unroll
            for (int r = 0; r < 4; r++) {
#pragma unroll
                for (int c = 0; c < 4; c++) {
                    pstep(aP[r].x, bP[c].x, wP.x, accP[r][c]);
                    pstep(aP[r].y, bP[c].y, wP.y, accP[r][c]);
                }
            }
        }
    }

    const float C = g_C;
#pragma unroll
    for (int r = 0; r < 4; r++) {
#pragma unroll
        for (int c = 0; c < 4; c++) {
            float lo, hi;
            unpack2(accP[r][c], lo, hi);
            out[(size_t)(i0 + ty + 16 * r) * NTOK + (j0 + tx + 16 * c)]
                = C + (lo + hi);
        }
    }
}

// ---------------------------------------------------------------------------
extern "C" void kernel_launch(void* const* d_in, const int* in_sizes, int n_in,
                              void* d_out, int out_size) {
    const float* l0   = (const float*)d_in[0];   // lstms0 [1024,256]
    const float* l1   = (const float*)d_in[1];   // lstms1 [1024,256]
    const float* Wfoh = (const float*)d_in[2];   // [512,512]
    const float* Wfom = (const float*)d_in[3];   // [512,512]
    const float* catB = (const float*)d_in[4];   // [1,1024]
    const float* h2L  = (const float*)d_in[5];   // [1024,256]
    const float* h2B  = (const float*)d_in[6];   // [1,256]
    const float* outL = (const float*)d_in[7];   // [256,1]
    const float* outB = (const float*)d_in[8];   // [1,1]
    float* out = (float*)d_out;                  // [1024,1024]

    gemm1_tanh<<<dim3(16, 16), 256>>>(l0, l1, Wfoh, Wfom, catB);
    gemm2_exp<<<dim3(8, 16), 256>>>(h2L, h2B);
    sumw_kernel<<<1, 256>>>(outL, outB);
    pairwise_kernel<<<256, 256>>>(outL, out);
}

// round 15
// speedup vs baseline: 1.2916x; 1.2348x over previous
#include <cuda_runtime.h>
#include <cstdint>

// Shapes (fixed): n=1024 tokens, 2L=512, H=512, H2=256.
#define NTOK 1024
#define KIN  512
#define HH   512
#define H2D  256
#define NPAIR 128                         // H2/2 pair-merged terms
#define SCALE_2LOG2E 2.885390081777927f   // 2*log2(e)
#define ONE2 0x3F8000003F800000ULL        // (1.0f, 1.0f) packed

// Scratch (device globals; no allocations allowed)
__device__ float g_ah[NTOK * HH];
__device__ float g_am[NTOK * HH];
__device__ float g_Ep1[NTOK * NPAIR];  // ex2 at even h (head side)
__device__ float g_Ep2[NTOK * NPAIR];  // ex2 at odd  h (head side)
__device__ float g_Eq1[NTOK * NPAIR];  // ex2 at even h (mod side, bias folded)
__device__ float g_Eq2[NTOK * NPAIR];  // ex2 at odd  h
__device__ float g_w1[NPAIR];          // -2*w[2p]
__device__ float g_w2[NPAIR];          // -2*w[2p+1]
__device__ float g_C;                  // sum(w) + outBias

// ---------------- packed f32x2 helpers (sm_103a FFMA2 path) ----------------
__device__ __forceinline__ uint64_t fma2(uint64_t a, uint64_t b, uint64_t c) {
    uint64_t d;
    asm("fma.rn.f32x2 %0, %1, %2, %3;" : "=l"(d) : "l"(a), "l"(b), "l"(c));
    return d;
}
__device__ __forceinline__ uint64_t mul2(uint64_t a, uint64_t b) {
    uint64_t d;
    asm("mul.rn.f32x2 %0, %1, %2;" : "=l"(d) : "l"(a), "l"(b));
    return d;
}
__device__ __forceinline__ uint64_t pack2(float lo, float hi) {
    uint64_t d;
    asm("mov.b64 %0, {%1, %2};" : "=l"(d) : "f"(lo), "f"(hi));
    return d;
}
__device__ __forceinline__ void unpack2(uint64_t p, float& lo, float& hi) {
    asm("mov.b64 {%0, %1}, %2;" : "=f"(lo), "=f"(hi) : "l"(p));
}
__device__ __forceinline__ uint64_t splat2(float v) {
    uint64_t d;
    asm("mov.b64 %0, {%1, %1};" : "=l"(d) : "f"(v));
    return d;
}
__device__ __forceinline__ float rcpf(float x) {
    float r;
    asm("rcp.approx.f32 %0, %1;" : "=f"(r) : "f"(x));
    return r;
}
__device__ __forceinline__ float fast_tanh(float x) {   // 1 - 2/(exp(2x)+1)
    float e;
    asm("ex2.approx.f32 %0, %1;" : "=f"(e) : "f"(x * SCALE_2LOG2E));
    return 1.0f - 2.0f * rcpf(e + 1.0f);
}
__device__ __forceinline__ float fast_ex2(float x) {
    float e;
    asm("ex2.approx.f32 %0, %1;" : "=f"(e) : "f"(x));
    return e;
}

// ---------------------------------------------------------------------------
// Kernel 1: [ah | am] = tanh( x @ [W_foh | W_fom] + catBias )
// 64x64 tile, BK=16, 256 threads, 4x4 micro (acc packed f32x2 along j),
// double-buffered smem. Grid (16,16) = 256 blocks.
// ---------------------------------------------------------------------------
__global__ __launch_bounds__(256)
void gemm1_tanh(const float* __restrict__ l0, const float* __restrict__ l1,
                const float* __restrict__ Wfoh, const float* __restrict__ Wfom,
                const float* __restrict__ catBias) {
    __shared__ __align__(16) float As[2][16][68];   // As[buf][k][m]
    __shared__ __align__(16) float Bs[2][16][68];   // Bs[buf][k][n]

    const int tid = threadIdx.x;
    const int n0 = blockIdx.x * 64;        // combined N (0..1023)
    const int m0 = blockIdx.y * 64;

    const bool head = (n0 < 512);
    const float* __restrict__ W = head ? Wfoh : Wfom;
    const int   wcol = head ? n0 : (n0 - 512);
    float* __restrict__ out = head ? g_ah : g_am;

    const int tx = tid & 15;
    const int ty = tid >> 4;
    const int lm  = tid >> 2;              // 0..63 (A rows)
    const int lk4 = (tid & 3) * 4;         // 0,4,8,12
    const int lk  = tid >> 4;              // 0..15 (B k)
    const int ln  = (tid & 15) * 4;        // 0..60 (B n)

    float4 av = *(const float4*)(l0 + (size_t)(m0 + lm) * 256 + lk4);
    float4 bv = *(const float4*)(W + (size_t)lk * HH + wcol + ln);
    As[0][lk4 + 0][lm] = av.x;
    As[0][lk4 + 1][lm] = av.y;
    As[0][lk4 + 2][lm] = av.z;
    As[0][lk4 + 3][lm] = av.w;
    *(float4*)&Bs[0][lk][ln] = bv;
    __syncthreads();

    uint64_t accP[4][2] = {};              // [i][j-pair], f32x2
    int cur = 0;

    for (int k0 = 0; k0 < KIN; k0 += 16) {
        float4 av2, bv2;
        const int kn = k0 + 16;
        if (kn < KIN) {
            const float* __restrict__ xsrc =
                (kn < 256) ? (l0 + (size_t)(m0 + lm) * 256 + (kn + lk4))
                           : (l1 + (size_t)(m0 + lm) * 256 + (kn - 256 + lk4));
            av2 = *(const float4*)xsrc;
            bv2 = *(const float4*)(W + (size_t)(kn + lk) * HH + wcol + ln);
        }

#pragma unroll
        for (int kk = 0; kk < 16; kk++) {
            float4 a4 = *(const float4*)&As[cur][kk][ty * 4];
            ulonglong2 b2 = *(const ulonglong2*)&Bs[cur][kk][tx * 4];
            float aa[4] = {a4.x, a4.y, a4.z, a4.w};
#pragma unroll
            for (int i = 0; i < 4; i++) {
                uint64_t as = splat2(aa[i]);
                accP[i][0] = fma2(as, b2.x, accP[i][0]);
                accP[i][1] = fma2(as, b2.y, accP[i][1]);
            }
        }

        if (kn < KIN) {
            const int nxt = cur ^ 1;
            As[nxt][lk4 + 0][lm] = av2.x;
            As[nxt][lk4 + 1][lm] = av2.y;
            As[nxt][lk4 + 2][lm] = av2.z;
            As[nxt][lk4 + 3][lm] = av2.w;
            *(float4*)&Bs[nxt][lk][ln] = bv2;
            __syncthreads();
            cur = nxt;
        }
    }

    const float4 bias4 = *(const float4*)&catBias[n0 + tx * 4];
#pragma unroll
    for (int i = 0; i < 4; i++) {
        float s0, s1, s2, s3;
        unpack2(accP[i][0], s0, s1);
        unpack2(accP[i][1], s2, s3);
        float4 v;
        v.x = fast_tanh(s0 + bias4.x);
        v.y = fast_tanh(s1 + bias4.y);
        v.z = fast_tanh(s2 + bias4.z);
        v.w = fast_tanh(s3 + bias4.w);
        *(float4*)&out[(size_t)(m0 + ty * 4 + i) * HH + wcol + tx * 4] = v;
    }
}

// ---------------------------------------------------------------------------
// Kernel 2: E = ex2( c * (a @ W + bias) ), written DEINTERLEAVED by h-parity:
//   even cols -> g_E?1[pair], odd cols -> g_E?2[pair], pair = col/2.
// Grid (8,16) = 128 blocks; n0<256 -> head (Ep), else mod (Eq, bias).
// ---------------------------------------------------------------------------
__global__ __launch_bounds__(256)
void gemm2_exp(const float* __restrict__ h2L, const float* __restrict__ h2B) {
    __shared__ __align__(16) float As[2][16][68];
    __shared__ __align__(16) float Bs[2][16][68];

    const int tid = threadIdx.x;
    const int n0 = blockIdx.x * 64;        // combined N (0..511)
    const int m0 = blockIdx.y * 64;

    const bool isP = (n0 < 256);
    const float* __restrict__ Asrc = isP ? g_ah : g_am;
    const int   wrow = isP ? 0 : 512;
    const int   col0 = isP ? n0 : (n0 - 256);
    float* __restrict__ out1 = isP ? g_Ep1 : g_Eq1;
    float* __restrict__ out2 = isP ? g_Ep2 : g_Eq2;

    const int tx = tid & 15;
    const int ty = tid >> 4;
    const int lm  = tid >> 2;
    const int lk4 = (tid & 3) * 4;
    const int lk  = tid >> 4;
    const int ln  = (tid & 15) * 4;

    float4 av = *(const float4*)(Asrc + (size_t)(m0 + lm) * HH + lk4);
    float4 bv = *(const float4*)(h2L + (size_t)(wrow + lk) * H2D + col0 + ln);
    As[0][lk4 + 0][lm] = av.x;
    As[0][lk4 + 1][lm] = av.y;
    As[0][lk4 + 2][lm] = av.z;
    As[0][lk4 + 3][lm] = av.w;
    *(float4*)&Bs[0][lk][ln] = bv;
    __syncthreads();

    uint64_t accP[4][2] = {};
    int cur = 0;

    for (int k0 = 0; k0 < HH; k0 += 16) {
        float4 av2, bv2;
        const int kn = k0 + 16;
        if (kn < HH) {
            av2 = *(const float4*)(Asrc + (size_t)(m0 + lm) * HH + kn + lk4);
            bv2 = *(const float4*)(h2L + (size_t)(wrow + kn + lk) * H2D + col0 + ln);
        }

#pragma unroll
        for (int kk = 0; kk < 16; kk++) {
            float4 a4 = *(const float4*)&As[cur][kk][ty * 4];
            ulonglong2 b2 = *(const ulonglong2*)&Bs[cur][kk][tx * 4];
            float aa[4] = {a4.x, a4.y, a4.z, a4.w};
#pragma unroll
            for (int i = 0; i < 4; i++) {
                uint64_t as = splat2(aa[i]);
                accP[i][0] = fma2(as, b2.x, accP[i][0]);
                accP[i][1] = fma2(as, b2.y, accP[i][1]);
            }
        }

        if (kn < HH) {
            const int nxt = cur ^ 1;
            As[nxt][lk4 + 0][lm] = av2.x;
            As[nxt][lk4 + 1][lm] = av2.y;
            As[nxt][lk4 + 2][lm] = av2.z;
            As[nxt][lk4 + 3][lm] = av2.w;
            *(float4*)&Bs[nxt][lk][ln] = bv2;
            __syncthreads();
            cur = nxt;
        }
    }

    // Epilogue: cols col0+tx*4+{0..3}; parity split -> pair index (col0+tx*4)/2
    const int pidx = (col0 + tx * 4) >> 1;   // first of 2 pairs this thread owns
#pragma unroll
    for (int i = 0; i < 4; i++) {
        float s0, s1, s2, s3;
        unpack2(accP[i][0], s0, s1);
        unpack2(accP[i][1], s2, s3);
        float b0 = isP ? 0.0f : h2B[col0 + tx * 4 + 0];
        float b1 = isP ? 0.0f : h2B[col0 + tx * 4 + 1];
        float b2 = isP ? 0.0f : h2B[col0 + tx * 4 + 2];
        float b3 = isP ? 0.0f : h2B[col0 + tx * 4 + 3];
        float e0 = fast_ex2((s0 + b0) * SCALE_2LOG2E);  // even col
        float e1 = fast_ex2((s1 + b1) * SCALE_2LOG2E);  // odd col
        float e2 = fast_ex2((s2 + b2) * SCALE_2LOG2E);  // even col
        float e3 = fast_ex2((s3 + b3) * SCALE_2LOG2E);  // odd col
        const size_t row = (size_t)(m0 + ty * 4 + i) * NPAIR;
        *(float2*)&out1[row + pidx] = make_float2(e0, e2);
        *(float2*)&out2[row + pidx] = make_float2(e1, e3);
    }
}

// ---------------------------------------------------------------------------
// Kernel 3: g_C = sum(outLayer) + outBias; g_w1/g_w2 = -2*w split by parity
// ---------------------------------------------------------------------------
__global__ void sumw_kernel(const float* __restrict__ outL,
                            const float* __restrict__ outB) {
    __shared__ float s[256];
    const int t = threadIdx.x;
    s[t] = outL[t];
    if (t < NPAIR) {
        g_w1[t] = -2.0f * outL[2 * t];
        g_w2[t] = -2.0f * outL[2 * t + 1];
    }
    __syncthreads();
    for (int o = 128; o > 0; o >>= 1) {
        if (t < o) s[t] += s[t + o];
        __syncthreads();
    }
    if (t == 0) g_C = s[0] + outB[0];
}

// ---------------------------------------------------------------------------
// Kernel 4: pairwise scores, pair-merged (0.5 MUFU / element):
//   per pair p: u1 = 1+Ep1*Eq1, u2 = 1+Ep2*Eq2
//   contribution = (w1*u2 + w2*u1) / (u1*u2)        [single rcp]
// Packed f32x2 over two adjacent pairs. 64x64 tile / block, 256 threads,
// 4x4 micro (rows ty+16r, cols tx+16c). Pairs in 4 chunks of 32.
// Row padding 36 floats = 144 B: 16-byte aligned rows (float4 staging OK),
// worst 2-way LDS.64 conflict, far below the MUFU budget.
// ---------------------------------------------------------------------------
__global__ __launch_bounds__(256, 2)
void pairwise_kernel(float* __restrict__ out) {
    __shared__ __align__(16) float E1p[64][36];
    __shared__ __align__(16) float E2p[64][36];
    __shared__ __align__(16) float E1q[64][36];
    __shared__ __align__(16) float E2q[64][36];
    __shared__ __align__(16) float ws1[NPAIR];
    __shared__ __align__(16) float ws2[NPAIR];

    const int tid = threadIdx.x;
    if (tid < NPAIR) {
        ws1[tid] = g_w1[tid];
        ws2[tid] = g_w2[tid];
    }

    const int j0 = (blockIdx.x & 15) * 64;
    const int i0 = (blockIdx.x >> 4) * 64;

    const int tx = tid & 15;
    const int ty = tid >> 4;

    uint64_t accP[4][4] = {};   // f32x2: lo = pair 2t, hi = pair 2t+1

    for (int ch = 0; ch < 4; ch++) {
        __syncthreads();   // ws visible (ch=0) / prior chunk reads done
        // Stage 64 rows x 32 pairs for each of the 4 arrays (512 float4 each)
#pragma unroll
        for (int p = 0; p < 2; p++) {
            int lin = tid + p * 256;       // 0..511
            int row = lin >> 3;            // 0..63
            int c   = (lin & 7) * 4;       // 0..28
            const size_t go = (size_t)(i0 + row) * NPAIR + ch * 32 + c;
            const size_t gq = (size_t)(j0 + row) * NPAIR + ch * 32 + c;
            *(float4*)&E1p[row][c] = *(const float4*)&g_Ep1[go];
            *(float4*)&E2p[row][c] = *(const float4*)&g_Ep2[go];
            *(float4*)&E1q[row][c] = *(const float4*)&g_Eq1[gq];
            *(float4*)&E2q[row][c] = *(const float4*)&g_Eq2[gq];
        }
        __syncthreads();

#pragma unroll 4
        for (int p2 = 0; p2 < 16; p2++) {  // 16 packed steps x 2 pairs
            uint64_t a1[4], a2[4], b1[4], b2[4];
#pragma unroll
            for (int r = 0; r < 4; r++) {
                a1[r] = *(const uint64_t*)&E1p[ty + 16 * r][2 * p2];
                a2[r] = *(const uint64_t*)&E2p[ty + 16 * r][2 * p2];
            }
#pragma unroll
            for (int c = 0; c < 4; c++) {
                b1[c] = *(const uint64_t*)&E1q[tx + 16 * c][2 * p2];
                b2[c] = *(const uint64_t*)&E2q[tx + 16 * c][2 * p2];
            }
            const uint64_t W1 = *(const uint64_t*)&ws1[ch * 32 + 2 * p2];
            const uint64_t W2 = *(const uint64_t*)&ws2[ch * 32 + 2 * p2];

#pragma unroll
            for (int r = 0; r < 4; r++) {
#pragma unroll
                for (int c = 0; c < 4; c++) {
                    uint64_t u1 = fma2(a1[r], b1[c], (uint64_t)ONE2);
                    uint64_t u2 = fma2(a2[r], b2[c], (uint64_t)ONE2);
                    uint64_t den = mul2(u1, u2);
                    uint64_t num = fma2(W1, u2, mul2(W2, u1));
                    float d0, d1;
                    unpack2(den, d0, d1);
                    uint64_t rr = pack2(rcpf(d0), rcpf(d1));
                    accP[r][c] = fma2(num, rr, accP[r][c]);
                }
            }
        }
    }

    const float C = g_C;
#pragma unroll
    for (int r = 0; r < 4; r++) {
#pragma unroll
        for (int c = 0; c < 4; c++) {
            float lo, hi;
            unpack2(accP[r][c], lo, hi);
            out[(size_t)(i0 + ty + 16 * r) * NTOK + (j0 + tx + 16 * c)]
                = C + (lo + hi);
        }
    }
}

// ---------------------------------------------------------------------------
extern "C" void kernel_launch(void* const* d_in, const int* in_sizes, int n_in,
                              void* d_out, int out_size) {
    const float* l0   = (const float*)d_in[0];   // lstms0 [1024,256]
    const float* l1   = (const float*)d_in[1];   // lstms1 [1024,256]
    const float* Wfoh = (const float*)d_in[2];   // [512,512]
    const float* Wfom = (const float*)d_in[3];   // [512,512]
    const float* catB = (const float*)d_in[4];   // [1,1024]
    const float* h2L  = (const float*)d_in[5];   // [1024,256]
    const float* h2B  = (const float*)d_in[6];   // [1,256]
    const float* outL = (const float*)d_in[7];   // [256,1]
    const float* outB = (const float*)d_in[8];   // [1,1]
    float* out = (float*)d_out;                  // [1024,1024]

    gemm1_tanh<<<dim3(16, 16), 256>>>(l0, l1, Wfoh, Wfom, catB);
    gemm2_exp<<<dim3(8, 16), 256>>>(h2L, h2B);
    sumw_kernel<<<1, 256>>>(outL, outB);
    pairwise_kernel<<<256, 256>>>(out);
}